// round 8
// baseline (speedup 1.0000x reference)
#include <cuda_runtime.h>
#include <cuda_fp16.h>
#include <cstdint>
#include <cstddef>

#define T_STEPS 8192
#define I_DIM   64
#define H_DIM   2048
#define O_DIM   128
#define R4H     8192
#define G_CTA   148
#define NTH     256
#define SMEM_W_BYTES (4 * 14 * H_DIM * 2)   // 229376 B: max 4*nu rows of fp16 weights

// ---------------- device-global scratch (no runtime allocation) -------------
__device__ __half   g_w16[(size_t)R4H * H_DIM];     // 32 MB  fp16 W_hh, CTA-permuted rows
__device__ float    g_xg[(size_t)T_STEPS * R4H];    // 256 MB x_gates [t][prow]
__device__ __half   g_h16[2][H_DIM];                // double-buffered hidden (fp16 broadcast)
__device__ float    g_hT[H_DIM];                    // final h in fp32
__device__ unsigned g_arrive;
__device__ unsigned g_release;

__host__ __device__ __forceinline__ int ubeg(int c) {
    return (int)(((long long)c * H_DIM) / G_CTA);
}

// Map original gate-major row r (gate gi, unit ug) -> permuted row (CTA-blocked)
__device__ __forceinline__ int permuted_row(int r) {
    int gi = r >> 11;
    int ug = r & (H_DIM - 1);
    int c = (int)(((long long)ug * G_CTA) / H_DIM);
    while (ubeg(c + 1) <= ug) c++;
    while (ubeg(c) > ug)      c--;
    int u0 = ubeg(c), nu = ubeg(c + 1) - u0;
    return 4 * u0 + gi * nu + (ug - u0);
}

// ---------------- init: reset cross-replay state -----------------------------
__global__ void init_k() {
    int i = blockIdx.x * blockDim.x + threadIdx.x;
    if (i < H_DIM) {
        g_h16[0][i] = __float2half_rn(0.0f);
        g_h16[1][i] = __float2half_rn(0.0f);
    }
    if (i == 0) { g_arrive = 0u; g_release = 0u; }
}

// ---------------- W_hh fp32 -> fp16, rows permuted into per-CTA blocks -------
__global__ __launch_bounds__(256) void prep_w(const float* __restrict__ Whh) {
    int r = blockIdx.x;
    size_t dst = (size_t)permuted_row(r) * H_DIM;
    size_t src = (size_t)r * H_DIM;
    for (int k = threadIdx.x; k < H_DIM; k += 256)
        g_w16[dst + k] = __float2half_rn(Whh[src + k]);
}

// ---------------- x_gates GEMM: g_xg[t][prow] = input[t]·W_ih[row] + biases --
__global__ __launch_bounds__(256) void xg_kernel(const float* __restrict__ inp,
                                                 const float* __restrict__ Wih,
                                                 const float* __restrict__ bih,
                                                 const float* __restrict__ bhh) {
    __shared__ float sI[64][64];    // [t][k]
    __shared__ float sW[64][65];    // [r][k] (+pad)
    int t0b = blockIdx.x * 64;
    int r0b = blockIdx.y * 64;
    int tid = threadIdx.x;

    for (int i = tid; i < 64 * 16; i += 256) {
        int row = i >> 4, q = i & 15;
        float4 v = *(const float4*)(inp + (size_t)(t0b + row) * I_DIM + q * 4);
        *(float4*)(&sI[row][q * 4]) = v;
        float4 w = *(const float4*)(Wih + (size_t)(r0b + row) * I_DIM + q * 4);
        sW[row][q * 4 + 0] = w.x; sW[row][q * 4 + 1] = w.y;
        sW[row][q * 4 + 2] = w.z; sW[row][q * 4 + 3] = w.w;
    }
    __syncthreads();

    int tx = tid & 15, ty = tid >> 4;   // tx -> rows (output-fast), ty -> t
    int rr = tx * 4, tt = ty * 4;
    float acc[4][4] = {};
#pragma unroll
    for (int k = 0; k < 64; k++) {
        float w0 = sW[rr + 0][k], w1 = sW[rr + 1][k];
        float w2 = sW[rr + 2][k], w3 = sW[rr + 3][k];
#pragma unroll
        for (int i = 0; i < 4; i++) {
            float x = sI[tt + i][k];
            acc[i][0] = fmaf(x, w0, acc[i][0]);
            acc[i][1] = fmaf(x, w1, acc[i][1]);
            acc[i][2] = fmaf(x, w2, acc[i][2]);
            acc[i][3] = fmaf(x, w3, acc[i][3]);
        }
    }
#pragma unroll
    for (int j = 0; j < 4; j++) {
        int r = r0b + rr + j;
        int prow = permuted_row(r);
        float b = bih[r] + bhh[r];
#pragma unroll
        for (int i = 0; i < 4; i++)
            g_xg[(size_t)(t0b + tt + i) * R4H + prow] = acc[i][j] + b;
    }
}

// ---------------- persistent recurrence kernel -------------------------------
__global__ __launch_bounds__(NTH, 1) void lstm_main(const float* __restrict__ Wlin,
                                                    const float* __restrict__ blin,
                                                    float* __restrict__ out) {
    extern __shared__ __half2 sWdyn[];      // [rows4][1024] half2, row-major
    __shared__ float sdot[64];
    __shared__ float sxg[64];
    __shared__ float swr[8];

    int cta  = blockIdx.x;
    int tid  = threadIdx.x;
    int wid  = tid >> 5;
    int lane = tid & 31;
    int u0 = ubeg(cta), nu = ubeg(cta + 1) - u0;
    int rows4 = 4 * nu;

    // Load this CTA's weight slab (contiguous after permutation) into SMEM
    {
        const float4* src = (const float4*)(g_w16 + (size_t)(4 * u0) * H_DIM);
        float4* dst = (float4*)sWdyn;
        int n16 = rows4 * (H_DIM / 8);
        for (int i = tid; i < n16; i += NTH) dst[i] = src[i];
    }
    float c_val = 0.0f;
    __syncthreads();

    for (int t = 0; t < T_STEPS; t++) {
        int buf = t & 1;
        const __half2* hp = (const __half2*)(g_h16[buf]);

        // Broadcast h into registers (L2, bypass stale L1)
        float2 hreg[32];
#pragma unroll
        for (int j = 0; j < 32; j++)
            hreg[j] = __half22float2(__ldcg(hp + j * 32 + lane));

        if (tid < rows4)
            sxg[tid] = __ldg(g_xg + (size_t)t * R4H + 4 * u0 + tid);

        // Row dot products: warp w owns rows w, w+8, ...
        for (int r = wid; r < rows4; r += 8) {
            const __half2* wr = sWdyn + (size_t)r * (H_DIM / 2);
            float a0 = 0.f, a1 = 0.f, a2 = 0.f, a3 = 0.f;
#pragma unroll
            for (int j = 0; j < 32; j += 4) {
                float2 f0 = __half22float2(wr[(j + 0) * 32 + lane]);
                float2 f1 = __half22float2(wr[(j + 1) * 32 + lane]);
                float2 f2 = __half22float2(wr[(j + 2) * 32 + lane]);
                float2 f3 = __half22float2(wr[(j + 3) * 32 + lane]);
                a0 = fmaf(f0.x, hreg[j + 0].x, fmaf(f0.y, hreg[j + 0].y, a0));
                a1 = fmaf(f1.x, hreg[j + 1].x, fmaf(f1.y, hreg[j + 1].y, a1));
                a2 = fmaf(f2.x, hreg[j + 2].x, fmaf(f2.y, hreg[j + 2].y, a2));
                a3 = fmaf(f3.x, hreg[j + 3].x, fmaf(f3.y, hreg[j + 3].y, a3));
            }
            float a = (a0 + a1) + (a2 + a3);
#pragma unroll
            for (int s = 16; s > 0; s >>= 1)
                a += __shfl_xor_sync(0xffffffffu, a, s);
            if (lane == 0) sdot[r] = a;
        }
        __syncthreads();

        // Cell update (fp32), one thread per hidden unit owned by this CTA
        if (tid < nu) {
            float xi = sdot[tid]           + sxg[tid];
            float xf = sdot[nu + tid]      + sxg[nu + tid];
            float xg = sdot[2 * nu + tid]  + sxg[2 * nu + tid];
            float xo = sdot[3 * nu + tid]  + sxg[3 * nu + tid];
            float ig = 1.0f / (1.0f + expf(-xi));
            float fg = 1.0f / (1.0f + expf(-xf));
            float gg = tanhf(xg);
            float og = 1.0f / (1.0f + expf(-xo));
            c_val = fg * c_val + ig * gg;
            float h = og * tanhf(c_val);
            g_h16[buf ^ 1][u0 + tid] = __float2half_rn(h);
            if (t == T_STEPS - 1) g_hT[u0 + tid] = h;
        }
        __syncthreads();

        // Grid-wide barrier: fence -> arrive; last arriver releases; rest poll
        if (tid == 0) {
            __threadfence();
            unsigned target = (unsigned)(t + 1) * (unsigned)G_CTA;
            unsigned prev = atomicAdd(&g_arrive, 1u);
            if (prev + 1u == target) {
                asm volatile("st.release.gpu.global.u32 [%0], %1;"
                             :: "l"(&g_release), "r"((unsigned)(t + 1)) : "memory");
            } else {
                unsigned v;
                do {
                    asm volatile("ld.acquire.gpu.global.u32 %0, [%1];"
                                 : "=r"(v) : "l"(&g_release) : "memory");
                } while (v < (unsigned)(t + 1));
            }
        }
        __syncthreads();
    }

    // Final linear: CTA o (< 128) computes out[o] = h_T · W_lin[o] + b_lin[o]
    if (cta < O_DIM) {
        const float* wrow = Wlin + (size_t)cta * H_DIM;
        float s = 0.0f;
#pragma unroll
        for (int i = 0; i < 8; i++) {
            int k = tid + i * NTH;
            s = fmaf(__ldcg(g_hT + k), __ldg(wrow + k), s);
        }
#pragma unroll
        for (int sh = 16; sh > 0; sh >>= 1)
            s += __shfl_xor_sync(0xffffffffu, s, sh);
        if (lane == 0) swr[wid] = s;
        __syncthreads();
        if (tid == 0) {
            float tot = 0.0f;
#pragma unroll
            for (int w = 0; w < 8; w++) tot += swr[w];
            out[cta] = tot + __ldg(blin + cta);
        }
    }
}

// ---------------- launch ------------------------------------------------------
extern "C" void kernel_launch(void* const* d_in, const int* in_sizes, int n_in,
                              void* d_out, int out_size) {
    const float* inp  = (const float*)d_in[0];
    const float* Wih  = (const float*)d_in[1];
    const float* Whh  = (const float*)d_in[2];
    const float* bih  = (const float*)d_in[3];
    const float* bhh  = (const float*)d_in[4];
    const float* Wlin = (const float*)d_in[5];
    const float* blin = (const float*)d_in[6];
    float* out = (float*)d_out;
    (void)in_sizes; (void)n_in; (void)out_size;

    cudaFuncSetAttribute(lstm_main, cudaFuncAttributeMaxDynamicSharedMemorySize,
                         SMEM_W_BYTES);

    init_k<<<(H_DIM + 255) / 256, 256>>>();
    prep_w<<<R4H, 256>>>(Whh);
    dim3 gx(T_STEPS / 64, R4H / 64);
    xg_kernel<<<gx, 256>>>(inp, Wih, bih, bhh);
    lstm_main<<<G_CTA, NTH, SMEM_W_BYTES>>>(Wlin, blin, out);
}

// round 11
// speedup vs baseline: 1.0325x; 1.0325x over previous
#include <cuda_runtime.h>
#include <cuda_fp16.h>
#include <cstdint>
#include <cstddef>

#define T_STEPS 8192
#define I_DIM   64
#define H_DIM   2048
#define O_DIM   128
#define R4H     8192
#define G_CTA   148
#define NTH     512
#define NWARP   16
#define SMEM_W_BYTES (4 * 14 * H_DIM * 2)   // 229376 B: max 4*nu rows of fp16 weights

// ---------------- device-global scratch (no runtime allocation) -------------
__device__ __half   g_w16[(size_t)R4H * H_DIM];     // 32 MB  fp16 W_hh, CTA-permuted rows
__device__ float    g_xg[(size_t)T_STEPS * R4H];    // 256 MB x_gates [t][prow]
__device__ __align__(16) __half g_h16[2][H_DIM];    // double-buffered hidden (fp16)
__device__ float    g_hT[H_DIM];                    // final h in fp32
__device__ unsigned g_arrive;
__device__ unsigned g_release;

__host__ __device__ __forceinline__ int ubeg(int c) {
    return (int)(((long long)c * H_DIM) / G_CTA);
}

// Map original gate-major row r (gate gi, unit ug) -> permuted row (CTA-blocked)
__device__ __forceinline__ int permuted_row(int r) {
    int gi = r >> 11;
    int ug = r & (H_DIM - 1);
    int c = (int)(((long long)ug * G_CTA) / H_DIM);
    while (ubeg(c + 1) <= ug) c++;
    while (ubeg(c) > ug)      c--;
    int u0 = ubeg(c), nu = ubeg(c + 1) - u0;
    return 4 * u0 + gi * nu + (ug - u0);
}

// ---------------- init: reset cross-replay state -----------------------------
__global__ void init_k() {
    int i = blockIdx.x * blockDim.x + threadIdx.x;
    if (i < H_DIM) {
        g_h16[0][i] = __float2half_rn(0.0f);
        g_h16[1][i] = __float2half_rn(0.0f);
    }
    if (i == 0) { g_arrive = 0u; g_release = 0u; }
}

// ---------------- W_hh fp32 -> fp16, rows permuted into per-CTA blocks -------
__global__ __launch_bounds__(256) void prep_w(const float* __restrict__ Whh) {
    int r = blockIdx.x;
    size_t dst = (size_t)permuted_row(r) * H_DIM;
    size_t src = (size_t)r * H_DIM;
    for (int k = threadIdx.x; k < H_DIM; k += 256)
        g_w16[dst + k] = __float2half_rn(Whh[src + k]);
}

// ---------------- x_gates GEMM: g_xg[t][prow] = input[t]·W_ih[row] + biases --
__global__ __launch_bounds__(256) void xg_kernel(const float* __restrict__ inp,
                                                 const float* __restrict__ Wih,
                                                 const float* __restrict__ bih,
                                                 const float* __restrict__ bhh) {
    __shared__ float sI[64][64];
    __shared__ float sW[64][65];
    int t0b = blockIdx.x * 64;
    int r0b = blockIdx.y * 64;
    int tid = threadIdx.x;

    for (int i = tid; i < 64 * 16; i += 256) {
        int row = i >> 4, q = i & 15;
        float4 v = *(const float4*)(inp + (size_t)(t0b + row) * I_DIM + q * 4);
        *(float4*)(&sI[row][q * 4]) = v;
        float4 w = *(const float4*)(Wih + (size_t)(r0b + row) * I_DIM + q * 4);
        sW[row][q * 4 + 0] = w.x; sW[row][q * 4 + 1] = w.y;
        sW[row][q * 4 + 2] = w.z; sW[row][q * 4 + 3] = w.w;
    }
    __syncthreads();

    int tx = tid & 15, ty = tid >> 4;
    int rr = tx * 4, tt = ty * 4;
    float acc[4][4] = {};
#pragma unroll
    for (int k = 0; k < 64; k++) {
        float w0 = sW[rr + 0][k], w1 = sW[rr + 1][k];
        float w2 = sW[rr + 2][k], w3 = sW[rr + 3][k];
#pragma unroll
        for (int i = 0; i < 4; i++) {
            float x = sI[tt + i][k];
            acc[i][0] = fmaf(x, w0, acc[i][0]);
            acc[i][1] = fmaf(x, w1, acc[i][1]);
            acc[i][2] = fmaf(x, w2, acc[i][2]);
            acc[i][3] = fmaf(x, w3, acc[i][3]);
        }
    }
#pragma unroll
    for (int j = 0; j < 4; j++) {
        int r = r0b + rr + j;
        int prow = permuted_row(r);
        float b = bih[r] + bhh[r];
#pragma unroll
        for (int i = 0; i < 4; i++)
            g_xg[(size_t)(t0b + tt + i) * R4H + prow] = acc[i][j] + b;
    }
}

// ---------------- persistent recurrence kernel -------------------------------
__global__ void __launch_bounds__(NTH, 1) lstm_main(const float* __restrict__ Wlin,
                                                    const float* __restrict__ blin,
                                                    float* __restrict__ out) {
    extern __shared__ uint4 sW[];           // [rows4][256] uint4 (4 half2 each)
    __shared__ float sdot[64];
    __shared__ float swr[NWARP];

    int cta  = blockIdx.x;
    int tid  = threadIdx.x;
    int wid  = tid >> 5;
    int lane = tid & 31;
    int u0 = ubeg(cta), nu = ubeg(cta + 1) - u0;
    int rows4 = 4 * nu;

    // Load this CTA's weight slab (contiguous after permutation) into SMEM
    {
        const float4* src = (const float4*)(g_w16 + (size_t)(4 * u0) * H_DIM);
        float4* dst = (float4*)sW;
        int n16 = rows4 * (H_DIM / 8);
        for (int i = tid; i < n16; i += NTH) dst[i] = src[i];
    }
    float c_val = 0.0f;
    __syncthreads();

    for (int t = 0; t < T_STEPS; t++) {
        // Wait until h(t) is globally published (release >= t). One poller/CTA.
        if (tid == 0) {
            unsigned v;
            do {
                asm volatile("ld.acquire.gpu.global.u32 %0, [%1];"
                             : "=r"(v) : "l"(&g_release) : "memory");
            } while (v < (unsigned)t);
        }
        __syncthreads();

        int buf = t & 1;
        // h broadcast: 8 x LDG.128 per lane, kept as half2 (no convert), L1-bypass
        const uint4* hp = (const uint4*)(g_h16[buf]);
        uint4 hv[8];
#pragma unroll
        for (int k = 0; k < 8; k++)
            hv[k] = __ldcg(hp + k * 32 + lane);

        // Prefetch this step's xg values into cell-lane registers (hidden by dot)
        float xg0 = 0.f, xg1 = 0.f, xg2 = 0.f, xg3 = 0.f;
        if (wid == 0 && lane < nu) {
            const float* xp = g_xg + (size_t)t * R4H + 4 * u0;
            xg0 = __ldcg(xp + lane);
            xg1 = __ldcg(xp + nu + lane);
            xg2 = __ldcg(xp + 2 * nu + lane);
            xg3 = __ldcg(xp + 3 * nu + lane);
        }

        // Row dot products: warp w owns rows w, w+16, ... (3-4 rows)
        for (int r = wid; r < rows4; r += NWARP) {
            const uint4* wr = sW + (size_t)r * (H_DIM / 8);
            __half2 c0, c1, c2, c3;
            {
                uint4 w = wr[lane];
                c0 = __hmul2(*(const __half2*)&w.x, *(const __half2*)&hv[0].x);
                c1 = __hmul2(*(const __half2*)&w.y, *(const __half2*)&hv[0].y);
                c2 = __hmul2(*(const __half2*)&w.z, *(const __half2*)&hv[0].z);
                c3 = __hmul2(*(const __half2*)&w.w, *(const __half2*)&hv[0].w);
            }
#pragma unroll
            for (int k = 1; k < 8; k++) {
                uint4 w = wr[k * 32 + lane];
                c0 = __hfma2(*(const __half2*)&w.x, *(const __half2*)&hv[k].x, c0);
                c1 = __hfma2(*(const __half2*)&w.y, *(const __half2*)&hv[k].y, c1);
                c2 = __hfma2(*(const __half2*)&w.z, *(const __half2*)&hv[k].z, c2);
                c3 = __hfma2(*(const __half2*)&w.w, *(const __half2*)&hv[k].w, c3);
            }
            float2 f0 = __half22float2(c0), f1 = __half22float2(c1);
            float2 f2 = __half22float2(c2), f3 = __half22float2(c3);
            float s = ((f0.x + f0.y) + (f1.x + f1.y)) + ((f2.x + f2.y) + (f3.x + f3.y));
#pragma unroll
            for (int sh = 16; sh > 0; sh >>= 1)
                s += __shfl_xor_sync(0xffffffffu, s, sh);
            if (lane == 0) sdot[r] = s;
        }
        __syncthreads();

        // Cell update (fp32) by warp 0; then release-arrive at the global barrier
        if (wid == 0) {
            if (lane < nu) {
                float xi = sdot[lane]           + xg0;
                float xf = sdot[nu + lane]      + xg1;
                float xg = sdot[2 * nu + lane]  + xg2;
                float xo = sdot[3 * nu + lane]  + xg3;
                float ig = 1.0f / (1.0f + expf(-xi));
                float fg = 1.0f / (1.0f + expf(-xf));
                float gg = tanhf(xg);
                float og = 1.0f / (1.0f + expf(-xo));
                c_val = fg * c_val + ig * gg;
                float h = og * tanhf(c_val);
                g_h16[buf ^ 1][u0 + lane] = __float2half_rn(h);
                if (t == T_STEPS - 1) g_hT[u0 + lane] = h;
            }
            __syncwarp();
            if (lane == 0) {
                unsigned prev, one = 1u;
                asm volatile("atom.release.gpu.global.add.u32 %0, [%1], %2;"
                             : "=r"(prev) : "l"(&g_arrive), "r"(one) : "memory");
                if (prev + 1u == (unsigned)(t + 1) * (unsigned)G_CTA) {
                    asm volatile("st.release.gpu.global.u32 [%0], %1;"
                                 :: "l"(&g_release), "r"((unsigned)(t + 1)) : "memory");
                }
            }
        }
        // Other warps loop straight to the next poll (waits inside tid==0 + bar)
    }

    // Final linear: CTA o (< 128) computes out[o] = h_T · W_lin[o] + b_lin[o]
    if (cta < O_DIM) {
        if (tid == 0) {
            unsigned v;
            do {
                asm volatile("ld.acquire.gpu.global.u32 %0, [%1];"
                             : "=r"(v) : "l"(&g_release) : "memory");
            } while (v < (unsigned)T_STEPS);
        }
        __syncthreads();

        const float* wrow = Wlin + (size_t)cta * H_DIM;
        float s = 0.0f;
#pragma unroll
        for (int i = 0; i < H_DIM / NTH; i++) {
            int k = tid + i * NTH;
            s = fmaf(__ldcg(g_hT + k), __ldg(wrow + k), s);
        }
#pragma unroll
        for (int sh = 16; sh > 0; sh >>= 1)
            s += __shfl_xor_sync(0xffffffffu, s, sh);
        if (lane == 0) swr[wid] = s;
        __syncthreads();
        if (tid == 0) {
            float tot = 0.0f;
#pragma unroll
            for (int w = 0; w < NWARP; w++) tot += swr[w];
            out[cta] = tot + __ldg(blin + cta);
        }
    }
}

// ---------------- launch ------------------------------------------------------
extern "C" void kernel_launch(void* const* d_in, const int* in_sizes, int n_in,
                              void* d_out, int out_size) {
    const float* inp  = (const float*)d_in[0];
    const float* Wih  = (const float*)d_in[1];
    const float* Whh  = (const float*)d_in[2];
    const float* bih  = (const float*)d_in[3];
    const float* bhh  = (const float*)d_in[4];
    const float* Wlin = (const float*)d_in[5];
    const float* blin = (const float*)d_in[6];
    float* out = (float*)d_out;
    (void)in_sizes; (void)n_in; (void)out_size;

    cudaFuncSetAttribute(lstm_main, cudaFuncAttributeMaxDynamicSharedMemorySize,
                         SMEM_W_BYTES);

    init_k<<<(H_DIM + 255) / 256, 256>>>();
    prep_w<<<R4H, 256>>>(Whh);
    dim3 gx(T_STEPS / 64, R4H / 64);
    xg_kernel<<<gx, 256>>>(inp, Wih, bih, bhh);
    lstm_main<<<G_CTA, NTH, SMEM_W_BYTES>>>(Wlin, blin, out);
}

// round 14
// speedup vs baseline: 1.1534x; 1.1170x over previous
#include <cuda_runtime.h>
#include <cuda_fp16.h>
#include <cstdint>
#include <cstddef>

#define T_STEPS 8192
#define I_DIM   64
#define H_DIM   2048
#define O_DIM   128
#define R4H     8192
#define G_CTA   148
#define NTH     512
#define NWARP   16
#define SMEM_W_BYTES (4 * 14 * H_DIM * 2)   // 229376 B: max 4*nu fp16 rows

// ---------------- device-global scratch (no runtime allocation) -------------
__device__ __half   g_w16[(size_t)R4H * H_DIM];     // 32 MB fp16 W_hh, unit-major rows
__device__ float    g_xg[(size_t)T_STEPS * R4H];    // 256 MB x_gates [t][4*unit+gate]
__device__ __align__(16) __half g_h16[2][H_DIM];    // double-buffered hidden (fp16)
__device__ float    g_hT[H_DIM];                    // final h in fp32
__device__ unsigned g_arrive;
__device__ unsigned g_release;

__host__ __device__ __forceinline__ int ubeg(int c) {
    return (int)(((long long)c * H_DIM) / G_CTA);
}

__device__ __forceinline__ float tanh_fast(float x) {
    float r;
    asm("tanh.approx.f32 %0, %1;" : "=f"(r) : "f"(x));
    return r;
}
__device__ __forceinline__ float sig_fast(float x) {
    return fmaf(tanh_fast(0.5f * x), 0.5f, 0.5f);
}

// ---------------- init: reset cross-replay state -----------------------------
__global__ void init_k() {
    int i = blockIdx.x * blockDim.x + threadIdx.x;
    if (i < H_DIM) {
        g_h16[0][i] = __float2half_rn(0.0f);
        g_h16[1][i] = __float2half_rn(0.0f);
    }
    if (i == 0) { g_arrive = 0u; g_release = 0u; }
}

// ---------------- W_hh fp32 -> fp16, rows permuted unit-major ----------------
// original row r = gate*2048 + unit  ->  prow = 4*unit + gate
__global__ __launch_bounds__(256) void prep_w(const float* __restrict__ Whh) {
    int r = blockIdx.x;
    int prow = 4 * (r & (H_DIM - 1)) + (r >> 11);
    size_t dst = (size_t)prow * H_DIM;
    size_t src = (size_t)r * H_DIM;
    for (int k = threadIdx.x; k < H_DIM; k += 256)
        g_w16[dst + k] = __float2half_rn(Whh[src + k]);
}

// ---------------- x_gates GEMM: g_xg[t][prow] = input[t]·W_ih[row] + biases --
__global__ __launch_bounds__(256) void xg_kernel(const float* __restrict__ inp,
                                                 const float* __restrict__ Wih,
                                                 const float* __restrict__ bih,
                                                 const float* __restrict__ bhh) {
    __shared__ float sI[64][64];
    __shared__ float sW[64][65];
    int t0b = blockIdx.x * 64;
    int r0b = blockIdx.y * 64;
    int tid = threadIdx.x;

    for (int i = tid; i < 64 * 16; i += 256) {
        int row = i >> 4, q = i & 15;
        float4 v = *(const float4*)(inp + (size_t)(t0b + row) * I_DIM + q * 4);
        *(float4*)(&sI[row][q * 4]) = v;
        float4 w = *(const float4*)(Wih + (size_t)(r0b + row) * I_DIM + q * 4);
        sW[row][q * 4 + 0] = w.x; sW[row][q * 4 + 1] = w.y;
        sW[row][q * 4 + 2] = w.z; sW[row][q * 4 + 3] = w.w;
    }
    __syncthreads();

    int tx = tid & 15, ty = tid >> 4;
    int rr = tx * 4, tt = ty * 4;
    float acc[4][4] = {};
#pragma unroll
    for (int k = 0; k < 64; k++) {
        float w0 = sW[rr + 0][k], w1 = sW[rr + 1][k];
        float w2 = sW[rr + 2][k], w3 = sW[rr + 3][k];
#pragma unroll
        for (int i = 0; i < 4; i++) {
            float x = sI[tt + i][k];
            acc[i][0] = fmaf(x, w0, acc[i][0]);
            acc[i][1] = fmaf(x, w1, acc[i][1]);
            acc[i][2] = fmaf(x, w2, acc[i][2]);
            acc[i][3] = fmaf(x, w3, acc[i][3]);
        }
    }
#pragma unroll
    for (int j = 0; j < 4; j++) {
        int r = r0b + rr + j;
        int prow = 4 * (r & (H_DIM - 1)) + (r >> 11);
        float b = bih[r] + bhh[r];
#pragma unroll
        for (int i = 0; i < 4; i++)
            g_xg[(size_t)(t0b + tt + i) * R4H + prow] = acc[i][j] + b;
    }
}

// ---------------- persistent recurrence kernel -------------------------------
__global__ void __launch_bounds__(NTH, 1) lstm_main(const float* __restrict__ Wlin,
                                                    const float* __restrict__ blin,
                                                    float* __restrict__ out) {
    extern __shared__ uint4 sW[];           // [rows4][256] uint4 (unit-major rows)
    __shared__ unsigned s_done;             // monotonic per-step completion count
    __shared__ unsigned s_flag;             // latest globally-published step
    __shared__ float    swr[NWARP];

    int cta  = blockIdx.x;
    int tid  = threadIdx.x;
    int wid  = tid >> 5;
    int lane = tid & 31;
    int u0 = ubeg(cta), nu = ubeg(cta + 1) - u0;   // nu in {13,14}
    int rows4 = 4 * nu;

    if (tid == 0) { s_done = 0u; s_flag = 0u; }

    // Load this CTA's weight slab (contiguous unit-major rows) into SMEM
    {
        const float4* src = (const float4*)(g_w16 + (size_t)(4 * u0) * H_DIM);
        float4* dst = (float4*)sW;
        int n16 = rows4 * (H_DIM / 8);
        for (int i = tid; i < n16; i += NTH) dst[i] = src[i];
    }
    __syncthreads();

    if (wid == 15) {
        // ---- dedicated poller warp: lane 0 spins on the global release flag,
        //      fences (L1 invalidate), and republishes into SMEM.
        if (lane == 0) {
            for (unsigned t = 1; t <= (unsigned)T_STEPS; t++) {
                unsigned v;
                do {
                    asm volatile("ld.acquire.gpu.global.u32 %0, [%1];"
                                 : "=r"(v) : "l"(&g_release) : "memory");
                } while (v < t);
                __threadfence();   // order + L1D invalidate for weak h loads
                asm volatile("st.release.cta.u32 [%0], %1;"
                             :: "l"(&s_flag), "r"(t) : "memory");
            }
        }
    } else if (wid == 14) {
        // ---- collector warp: lane 0 waits for all dot warps, then arrives
        //      at the global barrier (single atomic per CTA per step).
        if (lane == 0) {
            for (int t = 0; t < T_STEPS; t++) {
                unsigned tgt = (unsigned)(t + 1) * (unsigned)nu;
                unsigned v;
                do {
                    asm volatile("ld.acquire.cta.u32 %0, [%1];"
                                 : "=r"(v) : "l"(&s_done) : "memory");
                } while (v < tgt);
                unsigned prev;
                asm volatile("atom.release.gpu.global.add.u32 %0, [%1], %2;"
                             : "=r"(prev) : "l"(&g_arrive), "r"(1u) : "memory");
                if (prev + 1u == (unsigned)(t + 1) * (unsigned)G_CTA) {
                    asm volatile("st.release.gpu.global.u32 [%0], %1;"
                                 :: "l"(&g_release), "r"((unsigned)(t + 1)) : "memory");
                }
            }
        }
    } else if (wid < nu) {
        // ---- dot warp: owns hidden unit (u0 + wid); rows 4*wid .. 4*wid+3
        int ugl = u0 + wid;
        const uint4* wbase = sW + (size_t)(4 * wid) * (H_DIM / 8);
        float c_val = 0.0f;

        for (int t = 0; t < T_STEPS; t++) {
            // xg prefetch (immutable data; safe to issue before the spin)
            float4 xgv = make_float4(0.f, 0.f, 0.f, 0.f);
            if (lane == 0)
                xgv = *(const float4*)(g_xg + (size_t)t * R4H + 4 * ugl);

            // wait for h(t) publication (SMEM spin, ~LDS granularity)
            unsigned f;
            do {
                asm volatile("ld.acquire.cta.u32 %0, [%1];"
                             : "=r"(f) : "l"(&s_flag) : "memory");
            } while (f < (unsigned)t);

            // h broadcast: weak L1-cached loads (fresh after poller's fence)
            const uint4* hp = (const uint4*)(g_h16[t & 1]);
            uint4 hv[8];
#pragma unroll
            for (int k = 0; k < 8; k++) hv[k] = hp[k * 32 + lane];

            // 4 gate-row dots (i,f,g,o of this unit)
            float s[4];
#pragma unroll
            for (int j = 0; j < 4; j++) {
                const uint4* wr = wbase + (size_t)j * (H_DIM / 8);
                uint4 w = wr[lane];
                __half2 c0 = __hmul2(*(const __half2*)&w.x, *(const __half2*)&hv[0].x);
                __half2 c1 = __hmul2(*(const __half2*)&w.y, *(const __half2*)&hv[0].y);
                __half2 c2 = __hmul2(*(const __half2*)&w.z, *(const __half2*)&hv[0].z);
                __half2 c3 = __hmul2(*(const __half2*)&w.w, *(const __half2*)&hv[0].w);
#pragma unroll
                for (int k = 1; k < 8; k++) {
                    w = wr[k * 32 + lane];
                    c0 = __hfma2(*(const __half2*)&w.x, *(const __half2*)&hv[k].x, c0);
                    c1 = __hfma2(*(const __half2*)&w.y, *(const __half2*)&hv[k].y, c1);
                    c2 = __hfma2(*(const __half2*)&w.z, *(const __half2*)&hv[k].z, c2);
                    c3 = __hfma2(*(const __half2*)&w.w, *(const __half2*)&hv[k].w, c3);
                }
                float2 f0 = __half22float2(c0), f1 = __half22float2(c1);
                float2 f2 = __half22float2(c2), f3 = __half22float2(c3);
                s[j] = ((f0.x + f0.y) + (f1.x + f1.y)) + ((f2.x + f2.y) + (f3.x + f3.y));
            }

            // 4 interleaved butterfly reductions
#pragma unroll
            for (int sh = 16; sh > 0; sh >>= 1) {
                s[0] += __shfl_xor_sync(0xffffffffu, s[0], sh);
                s[1] += __shfl_xor_sync(0xffffffffu, s[1], sh);
                s[2] += __shfl_xor_sync(0xffffffffu, s[2], sh);
                s[3] += __shfl_xor_sync(0xffffffffu, s[3], sh);
            }

            // warp-local cell update + publish
            if (lane == 0) {
                float xi = s[0] + xgv.x;
                float xf = s[1] + xgv.y;
                float xg = s[2] + xgv.z;
                float xo = s[3] + xgv.w;
                float ig = sig_fast(xi);
                float fg = sig_fast(xf);
                float gg = tanh_fast(xg);
                float og = sig_fast(xo);
                c_val = fg * c_val + ig * gg;
                float h = og * tanh_fast(c_val);
                g_h16[(t & 1) ^ 1][ugl] = __float2half_rn(h);
                if (t == T_STEPS - 1) g_hT[ugl] = h;
                __threadfence();                  // h gpu-visible before arrive
                atomicAdd_block(&s_done, 1u);
            }
        }
    }
    // idle warps (wid in [nu,14)) fall through directly

    __syncthreads();

    // ---- final linear: CTA o (< 128) computes out[o] = h_T · W_lin[o] + b ----
    if (cta < O_DIM) {
        if (tid == 0) {
            unsigned v;
            do {
                asm volatile("ld.acquire.gpu.global.u32 %0, [%1];"
                             : "=r"(v) : "l"(&g_release) : "memory");
            } while (v < (unsigned)T_STEPS);
            __threadfence();
        }
        __syncthreads();

        const float* wrow = Wlin + (size_t)cta * H_DIM;
        float s = 0.0f;
#pragma unroll
        for (int i = 0; i < H_DIM / NTH; i++) {
            int k = tid + i * NTH;
            s = fmaf(g_hT[k], __ldg(wrow + k), s);
        }
#pragma unroll
        for (int sh = 16; sh > 0; sh >>= 1)
            s += __shfl_xor_sync(0xffffffffu, s, sh);
        if (lane == 0) swr[wid] = s;
        __syncthreads();
        if (tid == 0) {
            float tot = 0.0f;
#pragma unroll
            for (int w = 0; w < NWARP; w++) tot += swr[w];
            out[cta] = tot + __ldg(blin + cta);
        }
    }
}

// ---------------- launch ------------------------------------------------------
extern "C" void kernel_launch(void* const* d_in, const int* in_sizes, int n_in,
                              void* d_out, int out_size) {
    const float* inp  = (const float*)d_in[0];
    const float* Wih  = (const float*)d_in[1];
    const float* Whh  = (const float*)d_in[2];
    const float* bih  = (const float*)d_in[3];
    const float* bhh  = (const float*)d_in[4];
    const float* Wlin = (const float*)d_in[5];
    const float* blin = (const float*)d_in[6];
    float* out = (float*)d_out;
    (void)in_sizes; (void)n_in; (void)out_size;

    cudaFuncSetAttribute(lstm_main, cudaFuncAttributeMaxDynamicSharedMemorySize,
                         SMEM_W_BYTES);

    init_k<<<(H_DIM + 255) / 256, 256>>>();
    prep_w<<<R4H, 256>>>(Whh);
    dim3 gx(T_STEPS / 64, R4H / 64);
    xg_kernel<<<gx, 256>>>(inp, Wih, bih, bhh);
    lstm_main<<<G_CTA, NTH, SMEM_W_BYTES>>>(Wlin, blin, out);
}

// round 15
// speedup vs baseline: 1.2666x; 1.0982x over previous
#include <cuda_runtime.h>
#include <cuda_fp16.h>
#include <cstdint>
#include <cstddef>

#define T_STEPS 8192
#define I_DIM   64
#define H_DIM   2048
#define O_DIM   128
#define R4H     8192
#define G_CTA   148
#define NTH     480
#define NWARP   15
#define POLL_W  14
#define NREP    8
// dyn smem: 42 weight rows (3 per unit, 14 units) + 4KB h buffer
#define SMEM_DYN_BYTES (42 * 4096 + 4096)

// ---------------- device-global scratch (no runtime allocation) -------------
__device__ __half   g_w16[(size_t)R4H * H_DIM];     // 32 MB fp16 W_hh, unit-major rows
__device__ float    g_xg[(size_t)T_STEPS * R4H];    // 256 MB x_gates [t][4*unit+gate]
__device__ __align__(16) __half g_hrep[NREP][2][H_DIM];  // replicated, double-buffered h
__device__ float    g_hT[H_DIM];                    // final h in fp32
__device__ unsigned g_arrive;
__device__ unsigned g_release;

__host__ __device__ __forceinline__ int ubeg(int c) {
    return (int)(((long long)c * H_DIM) / G_CTA);
}

__device__ __forceinline__ float tanh_fast(float x) {
    float r;
    asm("tanh.approx.f32 %0, %1;" : "=f"(r) : "f"(x));
    return r;
}
__device__ __forceinline__ float sig_fast(float x) {
    return fmaf(tanh_fast(0.5f * x), 0.5f, 0.5f);
}

// ---------------- init: reset cross-replay state -----------------------------
__global__ void init_k() {
    if (blockIdx.x == 0 && threadIdx.x == 0) { g_arrive = 0u; g_release = 0u; }
}

// ---------------- W_hh fp32 -> fp16, rows permuted unit-major ----------------
// original row r = gate*2048 + unit  ->  prow = 4*unit + gate
__global__ __launch_bounds__(256) void prep_w(const float* __restrict__ Whh) {
    int r = blockIdx.x;
    int prow = 4 * (r & (H_DIM - 1)) + (r >> 11);
    size_t dst = (size_t)prow * H_DIM;
    size_t src = (size_t)r * H_DIM;
    for (int k = threadIdx.x; k < H_DIM; k += 256)
        g_w16[dst + k] = __float2half_rn(Whh[src + k]);
}

// ---------------- x_gates GEMM: g_xg[t][prow] = input[t]·W_ih[row] + biases --
__global__ __launch_bounds__(256) void xg_kernel(const float* __restrict__ inp,
                                                 const float* __restrict__ Wih,
                                                 const float* __restrict__ bih,
                                                 const float* __restrict__ bhh) {
    __shared__ float sI[64][64];
    __shared__ float sW[64][65];
    int t0b = blockIdx.x * 64;
    int r0b = blockIdx.y * 64;
    int tid = threadIdx.x;

    for (int i = tid; i < 64 * 16; i += 256) {
        int row = i >> 4, q = i & 15;
        float4 v = *(const float4*)(inp + (size_t)(t0b + row) * I_DIM + q * 4);
        *(float4*)(&sI[row][q * 4]) = v;
        float4 w = *(const float4*)(Wih + (size_t)(r0b + row) * I_DIM + q * 4);
        sW[row][q * 4 + 0] = w.x; sW[row][q * 4 + 1] = w.y;
        sW[row][q * 4 + 2] = w.z; sW[row][q * 4 + 3] = w.w;
    }
    __syncthreads();

    int tx = tid & 15, ty = tid >> 4;
    int rr = tx * 4, tt = ty * 4;
    float acc[4][4] = {};
#pragma unroll
    for (int k = 0; k < 64; k++) {
        float w0 = sW[rr + 0][k], w1 = sW[rr + 1][k];
        float w2 = sW[rr + 2][k], w3 = sW[rr + 3][k];
#pragma unroll
        for (int i = 0; i < 4; i++) {
            float x = sI[tt + i][k];
            acc[i][0] = fmaf(x, w0, acc[i][0]);
            acc[i][1] = fmaf(x, w1, acc[i][1]);
            acc[i][2] = fmaf(x, w2, acc[i][2]);
            acc[i][3] = fmaf(x, w3, acc[i][3]);
        }
    }
#pragma unroll
    for (int j = 0; j < 4; j++) {
        int r = r0b + rr + j;
        int prow = 4 * (r & (H_DIM - 1)) + (r >> 11);
        float b = bih[r] + bhh[r];
#pragma unroll
        for (int i = 0; i < 4; i++)
            g_xg[(size_t)(t0b + tt + i) * R4H + prow] = acc[i][j] + b;
    }
}

// ---------------- persistent recurrence kernel -------------------------------
__global__ void __launch_bounds__(NTH, 1) lstm_main(const float* __restrict__ Wlin,
                                                    const float* __restrict__ blin,
                                                    float* __restrict__ out) {
    extern __shared__ __align__(16) unsigned char smem_raw[];
    uint4* s_w = (uint4*)smem_raw;           // 42 rows x 256 uint4
    uint4* s_h = s_w + 42 * 256;             // 256 uint4 = 4KB h buffer
    __shared__ unsigned s_flag;              // latest step whose h is in s_h
    __shared__ unsigned s_done;              // per-CTA completed-unit counter
    __shared__ float    swr[NWARP];

    int cta  = blockIdx.x;
    int tid  = threadIdx.x;
    int wid  = tid >> 5;
    int lane = tid & 31;
    int u0 = ubeg(cta), nu = ubeg(cta + 1) - u0;   // 13 or 14

    if (tid == 0) { s_flag = 0u; s_done = 0u; }
    // zero s_h for step 0 (h(0) = 0)
    for (int i = tid; i < 256; i += NTH)
        s_h[i] = make_uint4(0u, 0u, 0u, 0u);

    // per-warp weight staging: rows 0..2 of the owned unit -> SMEM, row 3 -> regs
    uint4 wreg[8];
    int ugl = u0 + wid;
    if (wid < nu) {
        const uint4* wsrc = ((const uint4*)g_w16) + (size_t)(4 * ugl) * 256;
#pragma unroll
        for (int j = 0; j < 3; j++) {
            uint4* dst = s_w + (size_t)(3 * wid + j) * 256;
#pragma unroll
            for (int k = 0; k < 8; k++)
                dst[k * 32 + lane] = __ldg(wsrc + (size_t)j * 256 + k * 32 + lane);
        }
#pragma unroll
        for (int k = 0; k < 8; k++)
            wreg[k] = __ldg(wsrc + (size_t)3 * 256 + k * 32 + lane);
    }
    __syncthreads();

    if (wid == POLL_W) {
        // ---- poller warp: all lanes spin on release, fan h into SMEM -------
        const uint4* rep = (const uint4*)(g_hrep[cta & (NREP - 1)]);
        for (unsigned t = 1; t <= (unsigned)T_STEPS; t++) {
            unsigned v;
            do {
                asm volatile("ld.acquire.gpu.global.u32 %0, [%1];"
                             : "=r"(v) : "l"(&g_release) : "memory");
            } while (v < t);
            const uint4* src = rep + (size_t)(t & 1) * 256;
            uint4 a[8];
#pragma unroll
            for (int k = 0; k < 8; k++) a[k] = __ldcg(src + k * 32 + lane);
#pragma unroll
            for (int k = 0; k < 8; k++) s_h[k * 32 + lane] = a[k];
            asm volatile("bar.sync 1, 32;" ::: "memory");   // drain STS
            if (lane == 0)
                asm volatile("st.release.cta.u32 [%0], %1;"
                             :: "l"(&s_flag), "r"(t) : "memory");
        }
    } else if (wid < nu) {
        // ---- dot warp: owns hidden unit ugl; 3 SMEM rows + 1 register row --
        const uint4* wrow0 = s_w + (size_t)(3 * wid) * 256;
        float c_val = 0.0f;

        for (int t = 0; t < T_STEPS; t++) {
            // xg prefetch (immutable; overlaps the spin + barrier close)
            float4 xgv = make_float4(0.f, 0.f, 0.f, 0.f);
            if (lane == 0)
                xgv = *(const float4*)(g_xg + (size_t)t * R4H + 4 * ugl);

            // wait for h(t) in SMEM
            unsigned f;
            do {
                asm volatile("ld.acquire.cta.u32 %0, [%1];"
                             : "=r"(f) : "l"(&s_flag) : "memory");
            } while (f < (unsigned)t);

            // h from SMEM (8 LDS.128)
            uint4 hv[8];
#pragma unroll
            for (int k = 0; k < 8; k++) hv[k] = s_h[k * 32 + lane];

            float s[4];
            // rows 0..2 from SMEM
#pragma unroll
            for (int j = 0; j < 3; j++) {
                const uint4* wr = wrow0 + (size_t)j * 256;
                uint4 w = wr[lane];
                __half2 c0 = __hmul2(*(const __half2*)&w.x, *(const __half2*)&hv[0].x);
                __half2 c1 = __hmul2(*(const __half2*)&w.y, *(const __half2*)&hv[0].y);
                __half2 c2 = __hmul2(*(const __half2*)&w.z, *(const __half2*)&hv[0].z);
                __half2 c3 = __hmul2(*(const __half2*)&w.w, *(const __half2*)&hv[0].w);
#pragma unroll
                for (int k = 1; k < 8; k++) {
                    w = wr[k * 32 + lane];
                    c0 = __hfma2(*(const __half2*)&w.x, *(const __half2*)&hv[k].x, c0);
                    c1 = __hfma2(*(const __half2*)&w.y, *(const __half2*)&hv[k].y, c1);
                    c2 = __hfma2(*(const __half2*)&w.z, *(const __half2*)&hv[k].z, c2);
                    c3 = __hfma2(*(const __half2*)&w.w, *(const __half2*)&hv[k].w, c3);
                }
                float2 f0 = __half22float2(c0), f1 = __half22float2(c1);
                float2 f2 = __half22float2(c2), f3 = __half22float2(c3);
                s[j] = ((f0.x + f0.y) + (f1.x + f1.y)) + ((f2.x + f2.y) + (f3.x + f3.y));
            }
            // row 3 from registers
            {
                __half2 c0 = __hmul2(*(const __half2*)&wreg[0].x, *(const __half2*)&hv[0].x);
                __half2 c1 = __hmul2(*(const __half2*)&wreg[0].y, *(const __half2*)&hv[0].y);
                __half2 c2 = __hmul2(*(const __half2*)&wreg[0].z, *(const __half2*)&hv[0].z);
                __half2 c3 = __hmul2(*(const __half2*)&wreg[0].w, *(const __half2*)&hv[0].w);
#pragma unroll
                for (int k = 1; k < 8; k++) {
                    c0 = __hfma2(*(const __half2*)&wreg[k].x, *(const __half2*)&hv[k].x, c0);
                    c1 = __hfma2(*(const __half2*)&wreg[k].y, *(const __half2*)&hv[k].y, c1);
                    c2 = __hfma2(*(const __half2*)&wreg[k].z, *(const __half2*)&hv[k].z, c2);
                    c3 = __hfma2(*(const __half2*)&wreg[k].w, *(const __half2*)&hv[k].w, c3);
                }
                float2 f0 = __half22float2(c0), f1 = __half22float2(c1);
                float2 f2 = __half22float2(c2), f3 = __half22float2(c3);
                s[3] = ((f0.x + f0.y) + (f1.x + f1.y)) + ((f2.x + f2.y) + (f3.x + f3.y));
            }

#pragma unroll
            for (int sh = 16; sh > 0; sh >>= 1) {
                s[0] += __shfl_xor_sync(0xffffffffu, s[0], sh);
                s[1] += __shfl_xor_sync(0xffffffffu, s[1], sh);
                s[2] += __shfl_xor_sync(0xffffffffu, s[2], sh);
                s[3] += __shfl_xor_sync(0xffffffffu, s[3], sh);
            }

            if (lane == 0) {
                float xi = s[0] + xgv.x;
                float xf = s[1] + xgv.y;
                float xg = s[2] + xgv.z;
                float xo = s[3] + xgv.w;
                float ig = sig_fast(xi);
                float fg = sig_fast(xf);
                float gg = tanh_fast(xg);
                float og = sig_fast(xo);
                c_val = fg * c_val + ig * gg;
                float h = og * tanh_fast(c_val);
                __half hh = __float2half_rn(h);
                int buf = (t & 1) ^ 1;
#pragma unroll
                for (int r = 0; r < NREP; r++)
                    g_hrep[r][buf][ugl] = hh;
                if (t == T_STEPS - 1) g_hT[ugl] = h;
                __threadfence();                  // h visible before arrive
                unsigned prev = atomicAdd_block(&s_done, 1u);
                if (prev + 1u == (unsigned)(t + 1) * (unsigned)nu) {
                    // CTA-last unit: global arrive (+ release if chip-last)
                    unsigned pg;
                    asm volatile("atom.release.gpu.global.add.u32 %0, [%1], %2;"
                                 : "=r"(pg) : "l"(&g_arrive), "r"(1u) : "memory");
                    if (pg + 1u == (unsigned)(t + 1) * (unsigned)G_CTA) {
                        asm volatile("st.release.gpu.global.u32 [%0], %1;"
                                     :: "l"(&g_release), "r"((unsigned)(t + 1)) : "memory");
                    }
                }
            }
        }
    }
    // idle warp (wid in [nu, POLL_W)) falls straight through

    __syncthreads();   // poller exits only after release(T_STEPS) observed

    // ---- final linear: CTA o (< 128) computes out[o] = h_T · W_lin[o] + b ----
    if (cta < O_DIM) {
        const float* wrow = Wlin + (size_t)cta * H_DIM;
        float s = 0.0f;
        for (int k = tid; k < H_DIM; k += NTH)
            s = fmaf(__ldcg(g_hT + k), __ldg(wrow + k), s);
#pragma unroll
        for (int sh = 16; sh > 0; sh >>= 1)
            s += __shfl_xor_sync(0xffffffffu, s, sh);
        if (lane == 0) swr[wid] = s;
        __syncthreads();
        if (tid == 0) {
            float tot = 0.0f;
#pragma unroll
            for (int w = 0; w < NWARP; w++) tot += swr[w];
            out[cta] = tot + __ldg(blin + cta);
        }
    }
}

// ---------------- launch ------------------------------------------------------
extern "C" void kernel_launch(void* const* d_in, const int* in_sizes, int n_in,
                              void* d_out, int out_size) {
    const float* inp  = (const float*)d_in[0];
    const float* Wih  = (const float*)d_in[1];
    const float* Whh  = (const float*)d_in[2];
    const float* bih  = (const float*)d_in[3];
    const float* bhh  = (const float*)d_in[4];
    const float* Wlin = (const float*)d_in[5];
    const float* blin = (const float*)d_in[6];
    float* out = (float*)d_out;
    (void)in_sizes; (void)n_in; (void)out_size;

    cudaFuncSetAttribute(lstm_main, cudaFuncAttributeMaxDynamicSharedMemorySize,
                         SMEM_DYN_BYTES);

    init_k<<<1, 32>>>();
    prep_w<<<R4H, 256>>>(Whh);
    dim3 gx(T_STEPS / 64, R4H / 64);
    xg_kernel<<<gx, 256>>>(inp, Wih, bih, bhh);
    lstm_main<<<G_CTA, NTH, SMEM_DYN_BYTES>>>(Wlin, blin, out);
}